// round 1
// baseline (speedup 1.0000x reference)
#include <cuda_runtime.h>
#include <cstdint>

// ---------------- problem constants ----------------
#define N_EVENTS 400000
#define NTIMES   168
#define NLOCS    100000
#define NKEYS    (NLOCS * NTIMES)            // 16,800,000
#define NWORDS   ((NKEYS + 31) / 32)         // 525,000
#define D_LOC    64
#define D_TIME   32
#define D_USER   64
#define D_EMB    160
#define NOUT     256

// ---------------- scan config ----------------
#define SCAN_BLOCK 256
#define SCAN_WPT   16
#define SCAN_TILE  (SCAN_BLOCK * SCAN_WPT)                    // 4096 words/block
#define SCAN_NBLK  ((NWORDS + SCAN_TILE - 1) / SCAN_TILE)     // 129

// ---------------- scratch (static device memory: allocation-free) ----------------
__device__ uint32_t g_bitmap[NWORDS];
__device__ uint32_t g_wordbase[NWORDS];
__device__ uint32_t g_blocksums[SCAN_NBLK];
__device__ uint32_t g_counts[N_EVENTS];
__device__ uint32_t g_keyof[N_EVENTS];
__device__ float    g_usum[(size_t)N_EVENTS * D_USER];        // 102.4 MB
__device__ uint32_t g_nuniq[1];

// ---------------- K0: zero scratch ----------------
__global__ void k_zero() {
    int tid = blockIdx.x * blockDim.x + threadIdx.x;
    int stride = gridDim.x * blockDim.x;
    float4 z4 = make_float4(0.f, 0.f, 0.f, 0.f);
    float4* us = (float4*)g_usum;
    const int NUS4 = N_EVENTS * D_USER / 4;
    for (int i = tid; i < NUS4; i += stride) us[i] = z4;
    for (int i = tid; i < NWORDS; i += stride) g_bitmap[i] = 0u;
    for (int i = tid; i < N_EVENTS; i += stride) g_counts[i] = 0u;
}

// ---------------- K1: mark present keys ----------------
__global__ void k_mark(const int* __restrict__ x, const int* __restrict__ t) {
    int i = blockIdx.x * blockDim.x + threadIdx.x;
    if (i >= N_EVENTS) return;
    uint32_t key = (uint32_t)x[i] * NTIMES + (uint32_t)t[i];
    atomicOr(&g_bitmap[key >> 5], 1u << (key & 31u));
}

// ---------------- K2a: per-block popcount sums ----------------
__global__ void k_scan1() {
    __shared__ uint32_t ssum[SCAN_BLOCK / 32];
    int base = blockIdx.x * SCAN_TILE + threadIdx.x * SCAN_WPT;
    uint32_t s = 0;
#pragma unroll
    for (int q = 0; q < SCAN_WPT; q++) {
        int w = base + q;
        if (w < NWORDS) s += __popc(g_bitmap[w]);
    }
    for (int o = 16; o; o >>= 1) s += __shfl_down_sync(~0u, s, o);
    if ((threadIdx.x & 31) == 0) ssum[threadIdx.x >> 5] = s;
    __syncthreads();
    if (threadIdx.x == 0) {
        uint32_t tot = 0;
#pragma unroll
        for (int w = 0; w < SCAN_BLOCK / 32; w++) tot += ssum[w];
        g_blocksums[blockIdx.x] = tot;
    }
}

// ---------------- K2b: exclusive scan of block sums (tiny) ----------------
__global__ void k_scan2() {
    uint32_t run = 0;
    for (int i = 0; i < SCAN_NBLK; i++) {
        uint32_t v = g_blocksums[i];
        g_blocksums[i] = run;
        run += v;
    }
    g_nuniq[0] = run;
}

// ---------------- K2c: per-word exclusive rank base ----------------
__global__ void k_scan3() {
    __shared__ uint32_t swarp[SCAN_BLOCK / 32];
    int lane = threadIdx.x & 31, wid = threadIdx.x >> 5;
    int base = blockIdx.x * SCAN_TILE + threadIdx.x * SCAN_WPT;
    uint32_t pc[SCAN_WPT];
    uint32_t s = 0;
#pragma unroll
    for (int q = 0; q < SCAN_WPT; q++) {
        int w = base + q;
        pc[q] = (w < NWORDS) ? __popc(g_bitmap[w]) : 0u;
        s += pc[q];
    }
    uint32_t inc = s;
    for (int o = 1; o < 32; o <<= 1) {
        uint32_t v = __shfl_up_sync(~0u, inc, o);
        if (lane >= o) inc += v;
    }
    if (lane == 31) swarp[wid] = inc;
    __syncthreads();
    if (wid == 0) {
        uint32_t v = (lane < SCAN_BLOCK / 32) ? swarp[lane] : 0u;
        for (int o = 1; o < SCAN_BLOCK / 32; o <<= 1) {
            uint32_t vv = __shfl_up_sync(~0u, v, o);
            if (lane >= o) v += vv;
        }
        if (lane < SCAN_BLOCK / 32) swarp[lane] = v;   // inclusive warp sums
    }
    __syncthreads();
    uint32_t warpoff = (wid == 0) ? 0u : swarp[wid - 1];
    uint32_t run = g_blocksums[blockIdx.x] + warpoff + (inc - s);
#pragma unroll
    for (int q = 0; q < SCAN_WPT; q++) {
        int w = base + q;
        if (w < NWORDS) g_wordbase[w] = run;
        run += pc[q];
    }
}

// ---------------- K3: grouped sum of user embeddings + counts ----------------
// 16 threads per event; each thread RED-adds 4 floats of user_table[u].
__global__ void k_accum(const int* __restrict__ x, const int* __restrict__ t,
                        const int* __restrict__ u,
                        const float* __restrict__ user_table) {
    int gid = blockIdx.x * blockDim.x + threadIdx.x;
    int ev = gid >> 4;
    int lane = gid & 15;
    if (ev >= N_EVENTS) return;
    uint32_t key = (uint32_t)x[ev] * NTIMES + (uint32_t)t[ev];
    uint32_t w = key >> 5, bit = key & 31u;
    uint32_t j = g_wordbase[w] + __popc(g_bitmap[w] & ((1u << bit) - 1u));
    if (lane == 0) {
        atomicAdd(&g_counts[j], 1u);
        g_keyof[j] = key;   // dup writes store the same value: benign
    }
    int ui = u[ev];
    float4 v = ((const float4*)(user_table + (size_t)ui * D_USER))[lane];
    float* dst = &g_usum[(size_t)j * D_USER + lane * 4];
    atomicAdd(dst + 0, v.x);
    atomicAdd(dst + 1, v.y);
    atomicAdd(dst + 2, v.z);
    atomicAdd(dst + 3, v.w);
}

// ---------------- K4: fused gather + tf32 GEMM ----------------
#define BM 128
#define BN 128
#define AS_STRIDE 164   // 128x160 A tile, +4 pad (conflict-free fragment loads)
#define BS_STRIDE 136   // 160x128 B tile, +8 pad

__device__ __forceinline__ uint32_t f2tf32(float f) {
    uint32_t r;
    asm("cvt.rna.tf32.f32 %0, %1;" : "=r"(r) : "f"(f));
    return r;
}

extern __shared__ float smem[];

__global__ void __launch_bounds__(256)
k_gemm(const float* __restrict__ loc_table, const float* __restrict__ time_table,
       const float* __restrict__ W, const float* __restrict__ bvec,
       float* __restrict__ out) {
    float* As = smem;                        // [BM][AS_STRIDE]
    float* Bs = smem + BM * AS_STRIDE;       // [160][BS_STRIDE]
    const uint32_t nuniq = g_nuniq[0];
    const int rowBase = blockIdx.x * BM;
    const int colBase = blockIdx.y * BN;
    const int tid = threadIdx.x;

    // ---- gather A tile: [loc(64) | time(32) | u_mean(64)] per unique row ----
    {
        int r = tid >> 1;
        int part = tid & 1;                  // 2 threads per row, 20 float4 each
        uint32_t j = (uint32_t)(rowBase + r);
        if (j < nuniq) {
            uint32_t key = g_keyof[j];
            uint32_t xu = key / NTIMES, tu = key % NTIMES;
            float rcp = 1.0f / fmaxf((float)g_counts[j], 1.0f);
            const float4* locp = (const float4*)(loc_table + (size_t)xu * D_LOC);
            const float4* timp = (const float4*)(time_table + (size_t)tu * D_TIME);
            const float4* usp = (const float4*)(g_usum + (size_t)j * D_USER);
#pragma unroll
            for (int q = 0; q < 20; q++) {
                int f = part * 20 + q;       // 0..39
                float4 v;
                float sc = 1.0f;
                if (f < 16)      v = locp[f];
                else if (f < 24) v = timp[f - 16];
                else           { v = usp[f - 24]; sc = rcp; }
                float4 o;
                o.x = __uint_as_float(f2tf32(v.x * sc));
                o.y = __uint_as_float(f2tf32(v.y * sc));
                o.z = __uint_as_float(f2tf32(v.z * sc));
                o.w = __uint_as_float(f2tf32(v.w * sc));
                *(float4*)(&As[r * AS_STRIDE + f * 4]) = o;
            }
        } else {
            float4 z = make_float4(0.f, 0.f, 0.f, 0.f);
#pragma unroll
            for (int q = 0; q < 20; q++) {
                int f = part * 20 + q;
                *(float4*)(&As[r * AS_STRIDE + f * 4]) = z;
            }
        }
    }
    // ---- load B tile: W[k][colBase..colBase+127], tf32-rounded ----
    {
#pragma unroll
        for (int q = 0; q < 20; q++) {
            int idx = q * 256 + tid;         // 0..5119
            int k = idx >> 5;
            int n4 = idx & 31;
            float4 v = *(const float4*)(W + (size_t)k * NOUT + colBase + n4 * 4);
            float4 o;
            o.x = __uint_as_float(f2tf32(v.x));
            o.y = __uint_as_float(f2tf32(v.y));
            o.z = __uint_as_float(f2tf32(v.z));
            o.w = __uint_as_float(f2tf32(v.w));
            *(float4*)(&Bs[k * BS_STRIDE + n4 * 4]) = o;
        }
    }
    __syncthreads();

    // ---- mma mainloop: 8 warps as 4(m) x 2(n); warp tile 32x64 ----
    int warp = tid >> 5, lane = tid & 31;
    int wm = warp >> 1, wn = warp & 1;
    int gidr = lane >> 2, tig = lane & 3;
    float acc[2][8][4];
#pragma unroll
    for (int mi = 0; mi < 2; mi++)
#pragma unroll
        for (int ni = 0; ni < 8; ni++)
#pragma unroll
            for (int c = 0; c < 4; c++) acc[mi][ni][c] = 0.f;

    for (int kk = 0; kk < 20; kk++) {
        int k0 = kk * 8;
        uint32_t a[2][4];
#pragma unroll
        for (int mi = 0; mi < 2; mi++) {
            int arow = wm * 32 + mi * 16;
            a[mi][0] = __float_as_uint(As[(arow + gidr) * AS_STRIDE + k0 + tig]);
            a[mi][1] = __float_as_uint(As[(arow + gidr + 8) * AS_STRIDE + k0 + tig]);
            a[mi][2] = __float_as_uint(As[(arow + gidr) * AS_STRIDE + k0 + tig + 4]);
            a[mi][3] = __float_as_uint(As[(arow + gidr + 8) * AS_STRIDE + k0 + tig + 4]);
        }
#pragma unroll
        for (int ni = 0; ni < 8; ni++) {
            int bcol = wn * 64 + ni * 8;
            uint32_t b0 = __float_as_uint(Bs[(k0 + tig) * BS_STRIDE + bcol + gidr]);
            uint32_t b1 = __float_as_uint(Bs[(k0 + tig + 4) * BS_STRIDE + bcol + gidr]);
#pragma unroll
            for (int mi = 0; mi < 2; mi++) {
                asm volatile(
                    "mma.sync.aligned.m16n8k8.row.col.f32.tf32.tf32.f32 "
                    "{%0,%1,%2,%3}, {%4,%5,%6,%7}, {%8,%9}, {%0,%1,%2,%3};"
                    : "+f"(acc[mi][ni][0]), "+f"(acc[mi][ni][1]),
                      "+f"(acc[mi][ni][2]), "+f"(acc[mi][ni][3])
                    : "r"(a[mi][0]), "r"(a[mi][1]), "r"(a[mi][2]), "r"(a[mi][3]),
                      "r"(b0), "r"(b1));
            }
        }
    }

    // ---- epilogue: + b for valid rows, 0 for padded rows ----
#pragma unroll
    for (int mi = 0; mi < 2; mi++) {
#pragma unroll
        for (int ni = 0; ni < 8; ni++) {
            int col = colBase + wn * 64 + ni * 8 + 2 * tig;
            float bb0 = bvec[col], bb1 = bvec[col + 1];
            uint32_t row0 = (uint32_t)(rowBase + wm * 32 + mi * 16 + gidr);
            uint32_t row1 = row0 + 8;
            float2 v0, v1;
            if (row0 < nuniq) { v0.x = acc[mi][ni][0] + bb0; v0.y = acc[mi][ni][1] + bb1; }
            else              { v0.x = 0.f; v0.y = 0.f; }
            if (row1 < nuniq) { v1.x = acc[mi][ni][2] + bb0; v1.y = acc[mi][ni][3] + bb1; }
            else              { v1.x = 0.f; v1.y = 0.f; }
            *(float2*)(out + (size_t)row0 * NOUT + col) = v0;
            *(float2*)(out + (size_t)row1 * NOUT + col) = v1;
        }
    }
}

// ---------------- launcher ----------------
extern "C" void kernel_launch(void* const* d_in, const int* in_sizes, int n_in,
                              void* d_out, int out_size) {
    const int* x = (const int*)d_in[0];
    const int* t = (const int*)d_in[1];
    const int* u = (const int*)d_in[2];
    const float* loc_table = (const float*)d_in[3];
    const float* time_table = (const float*)d_in[4];
    const float* user_table = (const float*)d_in[5];
    const float* W = (const float*)d_in[6];
    const float* b = (const float*)d_in[7];
    float* out = (float*)d_out;

    static bool attr_done = false;
    const int smem_bytes = (BM * AS_STRIDE + 160 * BS_STRIDE) * 4;  // 171,008 B
    if (!attr_done) {
        cudaFuncSetAttribute(k_gemm, cudaFuncAttributeMaxDynamicSharedMemorySize,
                             smem_bytes);
        attr_done = true;
    }

    k_zero<<<4096, 256>>>();
    k_mark<<<(N_EVENTS + 255) / 256, 256>>>(x, t);
    k_scan1<<<SCAN_NBLK, SCAN_BLOCK>>>();
    k_scan2<<<1, 1>>>();
    k_scan3<<<SCAN_NBLK, SCAN_BLOCK>>>();
    k_accum<<<(N_EVENTS * 16 + 255) / 256, 256>>>(x, t, u, user_table);

    dim3 grid(N_EVENTS / BM, NOUT / BN);    // 3125 x 2
    k_gemm<<<grid, 256, smem_bytes>>>(loc_table, time_table, W, b, out);
}

// round 3
// speedup vs baseline: 1.3393x; 1.3393x over previous
#include <cuda_runtime.h>
#include <cstdint>

// ---------------- problem constants ----------------
#define N_EVENTS 400000
#define NTIMES   168
#define NLOCS    100000
#define NKEYS    (NLOCS * NTIMES)            // 16,800,000
#define NWORDS   ((NKEYS + 31) / 32)         // 525,000
#define D_LOC    64
#define D_TIME   32
#define D_USER   64
#define D_EMB    160
#define NOUT     256
#define NTILES   (N_EVENTS / 128)            // 3125

// ---------------- scan config ----------------
#define SCAN_BLOCK 256
#define SCAN_WPT   16
#define SCAN_TILE  (SCAN_BLOCK * SCAN_WPT)                    // 4096 words/block
#define SCAN_NBLK  ((NWORDS + SCAN_TILE - 1) / SCAN_TILE)     // 129

// ---------------- scratch (static device memory: allocation-free) ----------------
__device__ uint32_t g_bitmap[NWORDS];
__device__ uint32_t g_wordbase[NWORDS];
__device__ uint32_t g_blocksums[SCAN_NBLK];
__device__ uint32_t g_counts[N_EVENTS];
__device__ uint32_t g_keyof[N_EVENTS];
__device__ float    g_usum[(size_t)N_EVENTS * D_USER];        // 102.4 MB
__device__ uint32_t g_nuniq[1];
__device__ uint32_t g_Bfrag[D_EMB * NOUT];                    // 160KB W^T tf32, mma-fragment order

__device__ __forceinline__ uint32_t f2tf32(float f) {
    uint32_t r;
    asm("cvt.rna.tf32.f32 %0, %1;" : "=r"(r) : "f"(f));
    return r;
}

// ---------------- K0: zero scratch ----------------
__global__ void k_zero() {
    int tid = blockIdx.x * blockDim.x + threadIdx.x;
    int stride = gridDim.x * blockDim.x;
    float4 z4 = make_float4(0.f, 0.f, 0.f, 0.f);
    float4* us = (float4*)g_usum;
    const int NUS4 = N_EVENTS * D_USER / 4;
    for (int i = tid; i < NUS4; i += stride) us[i] = z4;
    for (int i = tid; i < NWORDS; i += stride) g_bitmap[i] = 0u;
    for (int i = tid; i < N_EVENTS; i += stride) g_counts[i] = 0u;
}

// ---------------- K1: mark present keys ----------------
__global__ void k_mark(const int* __restrict__ x, const int* __restrict__ t) {
    int i = blockIdx.x * blockDim.x + threadIdx.x;
    if (i >= N_EVENTS) return;
    uint32_t key = (uint32_t)x[i] * NTIMES + (uint32_t)t[i];
    atomicOr(&g_bitmap[key >> 5], 1u << (key & 31u));
}

// ---------------- K2a: per-block popcount sums ----------------
__global__ void k_scan1() {
    __shared__ uint32_t ssum[SCAN_BLOCK / 32];
    int base = blockIdx.x * SCAN_TILE + threadIdx.x * SCAN_WPT;
    uint32_t s = 0;
#pragma unroll
    for (int q = 0; q < SCAN_WPT; q++) {
        int w = base + q;
        if (w < NWORDS) s += __popc(g_bitmap[w]);
    }
    for (int o = 16; o; o >>= 1) s += __shfl_down_sync(~0u, s, o);
    if ((threadIdx.x & 31) == 0) ssum[threadIdx.x >> 5] = s;
    __syncthreads();
    if (threadIdx.x == 0) {
        uint32_t tot = 0;
#pragma unroll
        for (int w = 0; w < SCAN_BLOCK / 32; w++) tot += ssum[w];
        g_blocksums[blockIdx.x] = tot;
    }
}

// ---------------- K2b: parallel exclusive scan of 129 block sums ----------------
__global__ void k_scan2() {
    __shared__ uint32_t sw[8];
    int tid = threadIdx.x, lane = tid & 31, wid = tid >> 5;
    uint32_t v = (tid < SCAN_NBLK) ? g_blocksums[tid] : 0u;
    uint32_t inc = v;
    for (int o = 1; o < 32; o <<= 1) {
        uint32_t t = __shfl_up_sync(~0u, inc, o);
        if (lane >= o) inc += t;
    }
    if (lane == 31) sw[wid] = inc;
    __syncthreads();
    if (wid == 0) {
        uint32_t s = (lane < 8) ? sw[lane] : 0u;
        for (int o = 1; o < 8; o <<= 1) {
            uint32_t t = __shfl_up_sync(~0u, s, o);
            if (lane >= o) s += t;
        }
        if (lane < 8) sw[lane] = s;
    }
    __syncthreads();
    uint32_t off = wid ? sw[wid - 1] : 0u;
    uint32_t excl = off + inc - v;
    if (tid < SCAN_NBLK) g_blocksums[tid] = excl;
    if (tid == SCAN_NBLK - 1) g_nuniq[0] = excl + v;
}

// ---------------- K2c: per-word exclusive rank base ----------------
__global__ void k_scan3() {
    __shared__ uint32_t swarp[SCAN_BLOCK / 32];
    int lane = threadIdx.x & 31, wid = threadIdx.x >> 5;
    int base = blockIdx.x * SCAN_TILE + threadIdx.x * SCAN_WPT;
    uint32_t pc[SCAN_WPT];
    uint32_t s = 0;
#pragma unroll
    for (int q = 0; q < SCAN_WPT; q++) {
        int w = base + q;
        pc[q] = (w < NWORDS) ? __popc(g_bitmap[w]) : 0u;
        s += pc[q];
    }
    uint32_t inc = s;
    for (int o = 1; o < 32; o <<= 1) {
        uint32_t v = __shfl_up_sync(~0u, inc, o);
        if (lane >= o) inc += v;
    }
    if (lane == 31) swarp[wid] = inc;
    __syncthreads();
    if (wid == 0) {
        uint32_t v = (lane < SCAN_BLOCK / 32) ? swarp[lane] : 0u;
        for (int o = 1; o < SCAN_BLOCK / 32; o <<= 1) {
            uint32_t vv = __shfl_up_sync(~0u, v, o);
            if (lane >= o) v += vv;
        }
        if (lane < SCAN_BLOCK / 32) swarp[lane] = v;
    }
    __syncthreads();
    uint32_t warpoff = (wid == 0) ? 0u : swarp[wid - 1];
    uint32_t run = g_blocksums[blockIdx.x] + warpoff + (inc - s);
#pragma unroll
    for (int q = 0; q < SCAN_WPT; q++) {
        int w = base + q;
        if (w < NWORDS) g_wordbase[w] = run;
        run += pc[q];
    }
}

// ---------------- K3: grouped sum of user embeddings + counts ----------------
__global__ void k_accum(const int* __restrict__ x, const int* __restrict__ t,
                        const int* __restrict__ u,
                        const float* __restrict__ user_table) {
    int gid = blockIdx.x * blockDim.x + threadIdx.x;
    int ev = gid >> 4;
    int lane = gid & 15;
    if (ev >= N_EVENTS) return;
    uint32_t key = (uint32_t)x[ev] * NTIMES + (uint32_t)t[ev];
    uint32_t w = key >> 5, bit = key & 31u;
    uint32_t j = g_wordbase[w] + __popc(g_bitmap[w] & ((1u << bit) - 1u));
    if (lane == 0) {
        atomicAdd(&g_counts[j], 1u);
        g_keyof[j] = key;   // dup writes store the same value: benign
    }
    int ui = u[ev];
    float4 v = ((const float4*)(user_table + (size_t)ui * D_USER))[lane];
    float* dst = &g_usum[(size_t)j * D_USER + lane * 4];
    atomicAdd(dst + 0, v.x);
    atomicAdd(dst + 1, v.y);
    atomicAdd(dst + 2, v.z);
    atomicAdd(dst + 3, v.w);
}

// ---------------- K4a: W^T -> tf32 in mma-fragment order ----------------
// For m16n8k8 fragment B: thread lane L holds b0=B[k0+(L&3)][n0+(L>>2)],
// b1 at k0+4. Layout (floats):
//   idx = (((kk*4 + wn)*8 + ni)*64) + L*2 + reg
// with kk=k>>3, wn=n>>6, ni=(n&63)>>3, L=(n&7)*4+(k&3), reg=(k>>2)&1.
// K-half h occupies the contiguous float range [h*20480, h*20480+20480).
__global__ void k_prep(const float* __restrict__ W) {
    int idx = blockIdx.x * blockDim.x + threadIdx.x;
    if (idx >= D_EMB * NOUT) return;
    int n = idx % NOUT;
    int k = idx / NOUT;
    uint32_t bits = f2tf32(W[idx]);
    uint32_t kk = (uint32_t)k >> 3, wn = (uint32_t)n >> 6;
    uint32_t ni = ((uint32_t)n & 63u) >> 3;
    uint32_t L = ((uint32_t)n & 7u) * 4u + ((uint32_t)k & 3u);
    uint32_t reg = ((uint32_t)k >> 2) & 1u;
    uint32_t o = (((kk * 4u + wn) * 8u + ni) * 64u) + L * 2u + reg;
    g_Bfrag[o] = bits;
}

// ---------------- K4: fused gather + tf32 GEMM (128x256, 512 thr) ----------------
#define AS_STRIDE 164                          // 128 x 160 A tile, +4 pad
#define SM_A_FLOATS (128 * AS_STRIDE)          // 83,968 B
#define SM_B_FLOATS 20480                      // one 80KB K-half, fragment order
#define SM_BIAS_OFF (SM_A_FLOATS + SM_B_FLOATS)
#define SMEM_FLOATS (SM_BIAS_OFF + NOUT)
#define SMEM_BYTES  (SMEM_FLOATS * 4)

extern __shared__ float smem[];

__device__ __forceinline__ void load_bstage(int h, int tid) {
    const float4* src = (const float4*)(g_Bfrag + h * SM_B_FLOATS);
    float4* dst = (float4*)(smem + SM_A_FLOATS);
#pragma unroll
    for (int q = 0; q < SM_B_FLOATS / 4 / 512; q++)    // 10 float4 per thread
        dst[q * 512 + tid] = src[q * 512 + tid];
}

__global__ void __launch_bounds__(512, 1)
k_gemm(const float* __restrict__ loc_table, const float* __restrict__ time_table,
       const float* __restrict__ W, const float* __restrict__ bvec,
       float* __restrict__ out) {
    float* As = smem;
    float* Bs = smem + SM_A_FLOATS;
    const uint32_t nuniq = g_nuniq[0];
    const int rowBase = blockIdx.x * 128;
    const int tid = threadIdx.x;

    // ---- bias + B stage 0 ----
    if (tid < NOUT) smem[SM_BIAS_OFF + tid] = bvec[tid];
    load_bstage(0, tid);

    // ---- gather A tile (4 threads per row, 10 float4 each) ----
    {
        int r = tid >> 2;
        int part = tid & 3;
        uint32_t j = (uint32_t)(rowBase + r);
        if (j < nuniq) {
            uint32_t key = g_keyof[j];
            uint32_t xu = key / NTIMES, tu = key % NTIMES;
            float rcp = 1.0f / fmaxf((float)g_counts[j], 1.0f);
            const float4* locp = (const float4*)(loc_table + (size_t)xu * D_LOC);
            const float4* timp = (const float4*)(time_table + (size_t)tu * D_TIME);
            const float4* usp  = (const float4*)(g_usum + (size_t)j * D_USER);
#pragma unroll
            for (int q = 0; q < 10; q++) {
                int f = part * 10 + q;       // 0..39 float4s of the 160-float row
                float4 v;
                float sc = 1.0f;
                if (f < 16)      v = locp[f];
                else if (f < 24) v = timp[f - 16];
                else           { v = usp[f - 24]; sc = rcp; }
                float4 o;
                o.x = __uint_as_float(f2tf32(v.x * sc));
                o.y = __uint_as_float(f2tf32(v.y * sc));
                o.z = __uint_as_float(f2tf32(v.z * sc));
                o.w = __uint_as_float(f2tf32(v.w * sc));
                *(float4*)(&As[r * AS_STRIDE + f * 4]) = o;
            }
        } else {
            float4 z = make_float4(0.f, 0.f, 0.f, 0.f);
#pragma unroll
            for (int q = 0; q < 10; q++)
                *(float4*)(&As[r * AS_STRIDE + (part * 10 + q) * 4]) = z;
        }
    }
    __syncthreads();

    // ---- 16 warps: 4(m) x 4(n); warp tile 32 x 64 ----
    const int warp = tid >> 5, lane = tid & 31;
    const int wm = warp >> 2, wn = warp & 3;
    const int gidr = lane >> 2, tig = lane & 3;

    float acc[2][8][4];
#pragma unroll
    for (int mi = 0; mi < 2; mi++)
#pragma unroll
        for (int ni = 0; ni < 8; ni++)
#pragma unroll
            for (int c = 0; c < 4; c++) acc[mi][ni][c] = 0.f;

    const float* arow0 = &As[(wm * 32 + gidr) * AS_STRIDE + tig];

#pragma unroll 1
    for (int h = 0; h < 2; h++) {
        if (h == 1) {
            __syncthreads();
            load_bstage(1, tid);
            __syncthreads();
        }
#pragma unroll
        for (int kl = 0; kl < 10; kl++) {
            int k0 = (h * 10 + kl) * 8;
            uint32_t a[2][4];
#pragma unroll
            for (int mi = 0; mi < 2; mi++) {
                const float* ap = arow0 + mi * 16 * AS_STRIDE + k0;
                a[mi][0] = __float_as_uint(ap[0]);
                a[mi][1] = __float_as_uint(ap[8 * AS_STRIDE]);
                a[mi][2] = __float_as_uint(ap[4]);
                a[mi][3] = __float_as_uint(ap[8 * AS_STRIDE + 4]);
            }
            const float* bp = Bs + ((kl * 4 + wn) * 8) * 64 + lane * 2;
#pragma unroll
            for (int ni = 0; ni < 8; ni++) {
                float2 b01 = *(const float2*)(bp + ni * 64);
                uint32_t b0 = __float_as_uint(b01.x);
                uint32_t b1 = __float_as_uint(b01.y);
#pragma unroll
                for (int mi = 0; mi < 2; mi++) {
                    asm volatile(
                        "mma.sync.aligned.m16n8k8.row.col.f32.tf32.tf32.f32 "
                        "{%0,%1,%2,%3}, {%4,%5,%6,%7}, {%8,%9}, {%0,%1,%2,%3};"
                        : "+f"(acc[mi][ni][0]), "+f"(acc[mi][ni][1]),
                          "+f"(acc[mi][ni][2]), "+f"(acc[mi][ni][3])
                        : "r"(a[mi][0]), "r"(a[mi][1]), "r"(a[mi][2]), "r"(a[mi][3]),
                          "r"(b0), "r"(b1));
                }
            }
        }
    }

    // ---- epilogue ----
    const float* biases = smem + SM_BIAS_OFF;
#pragma unroll
    for (int mi = 0; mi < 2; mi++) {
#pragma unroll
        for (int ni = 0; ni < 8; ni++) {
            int col = wn * 64 + ni * 8 + 2 * tig;
            float bb0 = biases[col], bb1 = biases[col + 1];
            uint32_t row0 = (uint32_t)(rowBase + wm * 32 + mi * 16 + gidr);
            uint32_t row1 = row0 + 8;
            float2 v0, v1;
            if (row0 < nuniq) { v0.x = acc[mi][ni][0] + bb0; v0.y = acc[mi][ni][1] + bb1; }
            else              { v0.x = 0.f; v0.y = 0.f; }
            if (row1 < nuniq) { v1.x = acc[mi][ni][2] + bb0; v1.y = acc[mi][ni][3] + bb1; }
            else              { v1.x = 0.f; v1.y = 0.f; }
            *(float2*)(out + (size_t)row0 * NOUT + col) = v0;
            *(float2*)(out + (size_t)row1 * NOUT + col) = v1;
        }
    }
}

// ---------------- launcher ----------------
extern "C" void kernel_launch(void* const* d_in, const int* in_sizes, int n_in,
                              void* d_out, int out_size) {
    const int* x = (const int*)d_in[0];
    const int* t = (const int*)d_in[1];
    const int* u = (const int*)d_in[2];
    const float* loc_table = (const float*)d_in[3];
    const float* time_table = (const float*)d_in[4];
    const float* user_table = (const float*)d_in[5];
    const float* W = (const float*)d_in[6];
    const float* b = (const float*)d_in[7];
    float* out = (float*)d_out;

    static bool attr_done = false;
    if (!attr_done) {
        cudaFuncSetAttribute(k_gemm, cudaFuncAttributeMaxDynamicSharedMemorySize,
                             SMEM_BYTES);
        attr_done = true;
    }

    k_zero<<<4096, 256>>>();
    k_mark<<<(N_EVENTS + 255) / 256, 256>>>(x, t);
    k_scan1<<<SCAN_NBLK, SCAN_BLOCK>>>();
    k_scan2<<<1, 256>>>();
    k_scan3<<<SCAN_NBLK, SCAN_BLOCK>>>();
    k_accum<<<(N_EVENTS * 16 + 255) / 256, 256>>>(x, t, u, user_table);
    k_prep<<<(D_EMB * NOUT + 255) / 256, 256>>>(W);

    k_gemm<<<NTILES, 512, SMEM_BYTES>>>(loc_table, time_table, W, b, out);
}